// round 14
// baseline (speedup 1.0000x reference)
#include <cuda_runtime.h>
#include <cuda_bf16.h>
#include <cstdint>

#define NHN 50000
#define NGN 50000
#define NE  1600000
#define NGR 16

// ---------------- scratch (device globals; no allocations) ----------------
__device__ __align__(16) float g_H1[(size_t)NHN * 128];   // x_h@W1aL^T + b1a
__device__ __align__(16) float g_S [(size_t)NGN * 128];   // sum of leaky(z_e) per target
__device__ __align__(16) float g_T2[(size_t)NGN * 128];   // leaky(node-MLP stage1)
__device__ __align__(16) float g_WtH1[64 * 128];          // W1a[:, :64]^T (fp32 staging)
__device__ __align__(16) float g_WtN1[256 * 128];         // staging
__device__ __align__(16) float g_WtN2[128 * 128];         // staging
__device__ __align__(16) __nv_bfloat16 g_WtEh[64 * 128];  // W1a[:,64:]^T hi
__device__ __align__(16) __nv_bfloat16 g_WtEl[64 * 128];  // lo
__device__ __align__(16) __nv_bfloat16 g_WtH1h[64 * 128];
__device__ __align__(16) __nv_bfloat16 g_WtH1l[64 * 128];
__device__ __align__(16) __nv_bfloat16 g_WtN1h[256 * 128];
__device__ __align__(16) __nv_bfloat16 g_WtN1l[256 * 128];
__device__ __align__(16) __nv_bfloat16 g_WtN2h[128 * 128];
__device__ __align__(16) __nv_bfloat16 g_WtN2l[128 * 128];
__device__ __align__(16) float g_cvec[128];
__device__ __align__(16) float g_UW[NGR * 128];
__device__ int g_deg[NGN];
__device__ int g_is64_e;
__device__ int g_is64_b;

// ---------------- mma helpers ----------------
__device__ __forceinline__ uint32_t s2u(const void* p) {
    return (uint32_t)__cvta_generic_to_shared(p);
}
__device__ __forceinline__ void ldm4(uint32_t* r, uint32_t addr) {
    asm volatile("ldmatrix.sync.aligned.m8n8.x4.shared.b16 {%0,%1,%2,%3}, [%4];"
                 : "=r"(r[0]), "=r"(r[1]), "=r"(r[2]), "=r"(r[3]) : "r"(addr));
}
__device__ __forceinline__ void ldm4t(uint32_t* r, uint32_t addr) {
    asm volatile("ldmatrix.sync.aligned.m8n8.x4.trans.shared.b16 {%0,%1,%2,%3}, [%4];"
                 : "=r"(r[0]), "=r"(r[1]), "=r"(r[2]), "=r"(r[3]) : "r"(addr));
}
__device__ __forceinline__ void mma16816(float* d, const uint32_t* a, uint32_t b0, uint32_t b1) {
    asm volatile("mma.sync.aligned.m16n8k16.row.col.f32.bf16.bf16.f32 "
                 "{%0,%1,%2,%3}, {%4,%5,%6,%7}, {%8,%9}, {%0,%1,%2,%3};"
                 : "+f"(d[0]), "+f"(d[1]), "+f"(d[2]), "+f"(d[3])
                 : "r"(a[0]), "r"(a[1]), "r"(a[2]), "r"(a[3]), "r"(b0), "r"(b1));
}
__device__ __forceinline__ uint32_t cvt2bf(float lo, float hi) {
    uint32_t r;
    asm("cvt.rn.bf16x2.f32 %0, %1, %2;" : "=r"(r) : "f"(hi), "f"(lo));
    return r;
}

// ---------------- zero scratch + dtype detection ----------------
__global__ void k_zerodetect(const void* eidx, const void* batch) {
    if (blockIdx.x == 0 && threadIdx.x == 0) {
        const unsigned* p = (const unsigned*)eidx;
        int is64 = 1;
        for (int i = 0; i < 32; i++) {
            unsigned lo = p[2 * i], hi = p[2 * i + 1];
            if (hi != 0u || lo >= (unsigned)NHN) { is64 = 0; break; }
        }
        g_is64_e = is64;
        const unsigned* q = (const unsigned*)batch;
        int b64 = 1;
        for (int i = 0; i < 32; i++) {
            unsigned lo = q[2 * i], hi = q[2 * i + 1];
            if (hi != 0u || lo >= (unsigned)NGR) { b64 = 0; break; }
        }
        g_is64_b = b64;
    }
    long long n4 = (long long)NGN * 128 / 4;
    long long stride = (long long)gridDim.x * blockDim.x;
    for (long long i = (long long)blockIdx.x * blockDim.x + threadIdx.x; i < n4; i += stride)
        ((float4*)g_S)[i] = make_float4(0.f, 0.f, 0.f, 0.f);
    for (long long i = (long long)blockIdx.x * blockDim.x + threadIdx.x; i < NGN; i += stride)
        g_deg[i] = 0;
}

// ---------------- weight precompute / transposes ----------------
__global__ void k_prep(const float* __restrict__ W1a, const float* __restrict__ W1b,
                       const float* __restrict__ W2a, const float* __restrict__ W2b,
                       const float* __restrict__ b1b, const float* __restrict__ u) {
    int b = blockIdx.x, t = threadIdx.x;
    if (b < 128) {
        __shared__ float wrow[128];
        wrow[t] = W2a[b * 320 + 128 + t];
        __syncthreads();
        float s = 0.f;
        for (int p = 0; p < 128; p++) s += wrow[p] * W1b[p * 128 + t];
        g_WtN1[(128 + t) * 128 + b] = s;
        if (t == 0) {
            float c = 0.f;
            for (int p = 0; p < 128; p++) c += wrow[p] * b1b[p];
            g_cvec[b] = c;
        }
    } else if (b == 128) {
        for (int i = t; i < 64 * 128; i += 128) {
            int k = i >> 7, j = i & 127;
            g_WtH1[i] = W1a[j * 128 + k];
            float w = W1a[j * 128 + 64 + k];
            __nv_bfloat16 h = __float2bfloat16(w);
            g_WtEh[i] = h;
            g_WtEl[i] = __float2bfloat16(w - __bfloat162float(h));
        }
    } else if (b == 129) {
        for (int i = t; i < 128 * 128; i += 128) {
            int k = i >> 7, j = i & 127;
            g_WtN1[i] = W2a[j * 320 + k];
        }
    } else if (b == 130) {
        for (int i = t; i < 128 * 128; i += 128) {
            int k = i >> 7, j = i & 127;
            g_WtN2[i] = W2b[j * 128 + k];
        }
    } else {
        for (int i = t; i < NGR * 128; i += 128) {
            int g = i >> 7, j = i & 127;
            float s = 0.f;
            for (int k = 0; k < 64; k++) s += u[g * 64 + k] * W2a[j * 320 + 256 + k];
            g_UW[i] = s;
        }
    }
}

// split staged fp32 weights into bf16 hi/lo (after k_prep)
__global__ void k_split() {
    int i = blockIdx.x * blockDim.x + threadIdx.x;
    if (i < 8192) {
        float w = g_WtH1[i];
        __nv_bfloat16 h = __float2bfloat16(w);
        g_WtH1h[i] = h;
        g_WtH1l[i] = __float2bfloat16(w - __bfloat162float(h));
    } else if (i < 8192 + 32768) {
        int j = i - 8192;
        float w = g_WtN1[j];
        __nv_bfloat16 h = __float2bfloat16(w);
        g_WtN1h[j] = h;
        g_WtN1l[j] = __float2bfloat16(w - __bfloat162float(h));
    } else if (i < 8192 + 32768 + 16384) {
        int j = i - 8192 - 32768;
        float w = g_WtN2[j];
        __nv_bfloat16 h = __float2bfloat16(w);
        g_WtN2h[j] = h;
        g_WtN2l[j] = __float2bfloat16(w - __bfloat162float(h));
    }
}

// ---------------- shared split-store helper ----------------
__device__ __forceinline__ void split_store(__nv_bfloat16* Ah, __nv_bfloat16* Al,
                                            int off, float4 v) {
    uint32_t ph01 = cvt2bf(v.x, v.y);
    uint32_t ph23 = cvt2bf(v.z, v.w);
    float l0 = v.x - __uint_as_float(ph01 << 16);
    float l1 = v.y - __uint_as_float(ph01 & 0xffff0000u);
    float l2 = v.z - __uint_as_float(ph23 << 16);
    float l3 = v.w - __uint_as_float(ph23 & 0xffff0000u);
    uint32_t pl01 = cvt2bf(l0, l1);
    uint32_t pl23 = cvt2bf(l2, l3);
    *(uint2*)(Ah + off) = make_uint2(ph01, ph23);
    *(uint2*)(Al + off) = make_uint2(pl01, pl23);
}

// ================= tensor-core edge kernel: 256-edge block, 64x64 warp tiles =================
// 8 warps = 4M(64) x 2N(64); d[4][8][4] = 128 accum regs; 1 CTA/SM.
#define A2_STR 40     // bf16 per A row (32 + 8 pad)
#define B2_STR 136    // bf16 per B row (128 + 8 pad)
#define CS_STR 132    // f32 per Cs row (128 + 4 pad; kills 8-way store conflicts)
#define SE_AL 20480
#define SE_BH 40960
#define SE_BL 49664
#define SE_TOT 58368

extern __shared__ __align__(16) char smdyn[];

__launch_bounds__(256, 1)
__global__ void k_edge(const float* __restrict__ EA, const void* __restrict__ eidx) {
    __nv_bfloat16* Ah = (__nv_bfloat16*)smdyn;
    __nv_bfloat16* Al = (__nv_bfloat16*)(smdyn + SE_AL);
    __nv_bfloat16* Bh = (__nv_bfloat16*)(smdyn + SE_BH);
    __nv_bfloat16* Bl = (__nv_bfloat16*)(smdyn + SE_BL);
    float* Cs = (float*)smdyn;

    const int tid = threadIdx.x;
    const int lane = tid & 31, wid = tid >> 5;
    const int wm = (wid & 3) * 64;       // 4 warps in M, 64 rows each
    const int wn = (wid >> 2) * 64;      // 2 warps in N, 64 cols each
    const long long m0 = (long long)blockIdx.x * 256;

    float d[4][8][4];
#pragma unroll
    for (int mf = 0; mf < 4; mf++)
#pragma unroll
        for (int nf = 0; nf < 8; nf++)
#pragma unroll
            for (int e = 0; e < 4; e++) d[mf][nf][e] = 0.f;

    const uint32_t uAh = s2u(Ah), uAl = s2u(Al), uBh = s2u(Bh), uBl = s2u(Bl);

    for (int ks = 0; ks < 64; ks += 32) {
        // ---- stage A tile [256 x 32] fp32 -> bf16 hi/lo ----
#pragma unroll
        for (int it = 0; it < 8; it++) {
            int q = tid + it * 256;
            int m = q >> 3, k4 = q & 7;
            float4 v = ((const float4*)(EA + (m0 + m) * 64 + ks))[k4];
            split_store(Ah, Al, m * A2_STR + k4 * 4, v);
        }
        // ---- stage B tile rows [ks..ks+32) hi/lo ----
#pragma unroll
        for (int it = 0; it < 4; it++) {
            int q = tid + it * 256;
            int row = q >> 5, c = q & 31;
            int off = row * B2_STR + c * 4;
            *(uint2*)(Bh + off) = *(const uint2*)(g_WtEh + (ks + row) * 128 + c * 4);
            *(uint2*)(Bl + off) = *(const uint2*)(g_WtEl + (ks + row) * 128 + c * 4);
        }
        __syncthreads();

#pragma unroll
        for (int kc = 0; kc < 2; kc++) {
            uint32_t ah[4][4], al[4][4];
#pragma unroll
            for (int mf = 0; mf < 4; mf++) {
                uint32_t aoff = (uint32_t)(((wm + mf * 16 + (lane & 15)) * A2_STR +
                                            kc * 16 + ((lane >> 4) << 3)) * 2);
                ldm4(ah[mf], uAh + aoff);
                ldm4(al[mf], uAl + aoff);
            }
#pragma unroll
            for (int nf2 = 0; nf2 < 4; nf2++) {
                uint32_t boff = (uint32_t)(((kc * 16 + (lane & 15)) * B2_STR +
                                            wn + nf2 * 16 + ((lane >> 4) << 3)) * 2);
                uint32_t bh[4], bl[4];
                ldm4t(bh, uBh + boff);
                ldm4t(bl, uBl + boff);
#pragma unroll
                for (int mf = 0; mf < 4; mf++) {
#pragma unroll
                    for (int tt = 0; tt < 2; tt++) {
                        float* dd = d[mf][nf2 * 2 + tt];
                        mma16816(dd, ah[mf], bh[2 * tt], bh[2 * tt + 1]);
                        mma16816(dd, ah[mf], bl[2 * tt], bl[2 * tt + 1]);
                        mma16816(dd, al[mf], bh[2 * tt], bh[2 * tt + 1]);
                    }
                }
            }
        }
        __syncthreads();
    }

    // ---- epilogue: 4 passes of 64 rows; pass p staged by the 2 warps with (wid&3)==p ----
    const int is64 = g_is64_e;
    const int tx = tid & 15, ty = tid >> 4;
    const int c0 = tx * 8;
#pragma unroll
    for (int p = 0; p < 4; p++) {
        if ((wid & 3) == p) {
            int colc = wn + 2 * (lane & 3);
#pragma unroll
            for (int mf = 0; mf < 4; mf++) {
                int r0 = mf * 16 + (lane >> 2);
#pragma unroll
                for (int nf = 0; nf < 8; nf++) {
                    *(float2*)&Cs[r0 * CS_STR + colc + nf * 8] =
                        make_float2(d[mf][nf][0], d[mf][nf][1]);
                    *(float2*)&Cs[(r0 + 8) * CS_STR + colc + nf * 8] =
                        make_float2(d[mf][nf][2], d[mf][nf][3]);
                }
            }
        }
        __syncthreads();
#pragma unroll
        for (int rr = 0; rr < 4; rr++) {
            int cs_r = ty * 4 + rr;
            long long er = m0 + p * 64 + cs_r;
            long long s, t;
            if (is64) {
                s = ((const long long*)eidx)[er];
                t = ((const long long*)eidx)[(long long)NE + er];
            } else {
                s = ((const int*)eidx)[er];
                t = ((const int*)eidx)[(long long)NE + er];
            }
            const float4* h = (const float4*)(g_H1 + s * 128 + c0);
            float4 h0 = h[0], h1 = h[1];
            const float* cr = Cs + cs_r * CS_STR + c0;
            float v[8];
            v[0] = cr[0] + h0.x; v[1] = cr[1] + h0.y; v[2] = cr[2] + h0.z; v[3] = cr[3] + h0.w;
            v[4] = cr[4] + h1.x; v[5] = cr[5] + h1.y; v[6] = cr[6] + h1.z; v[7] = cr[7] + h1.w;
#pragma unroll
            for (int j = 0; j < 8; j++) v[j] = (v[j] >= 0.f) ? v[j] : 0.1f * v[j];
            float* dst = g_S + t * 128 + c0;
            asm volatile("red.global.add.v4.f32 [%0], {%1,%2,%3,%4};"
                         :: "l"(dst), "f"(v[0]), "f"(v[1]), "f"(v[2]), "f"(v[3]) : "memory");
            asm volatile("red.global.add.v4.f32 [%0], {%1,%2,%3,%4};"
                         :: "l"(dst + 4), "f"(v[4]), "f"(v[5]), "f"(v[6]), "f"(v[7]) : "memory");
            if (tx == 0) atomicAdd(&g_deg[(int)t], 1);
        }
        __syncthreads();
    }
}

// ================= tensor-core node GEMM: 64x128 block tile (R13, unchanged) =================
#define AN_STR 40
#define BN_STR 136
#define NSM_AL 5120
#define NSM_BH 10240
#define NSM_BL 18944
#define NSM_TOT 32768

template <int KTOT, int MODE>
__launch_bounds__(256, 2)
__global__ void k_tg(const float* __restrict__ A0, const float* __restrict__ bias,
                     float* __restrict__ Cout, int Mrows, const void* __restrict__ idx) {
    __shared__ __align__(16) char sm[NSM_TOT];
    __nv_bfloat16* Ah = (__nv_bfloat16*)sm;
    __nv_bfloat16* Al = (__nv_bfloat16*)(sm + NSM_AL);
    __nv_bfloat16* Bh = (__nv_bfloat16*)(sm + NSM_BH);
    __nv_bfloat16* Bl = (__nv_bfloat16*)(sm + NSM_BL);
    float* Cs = (float*)sm;

    const int tid = threadIdx.x;
    const int lane = tid & 31, wid = tid >> 5;
    const int wm = (wid & 3) * 16;
    const int wn = (wid >> 2) * 64;
    const int m0 = blockIdx.x * 64;

    const __nv_bfloat16* Wh = (MODE == 0) ? g_WtH1h : (MODE == 2) ? g_WtN1h : g_WtN2h;
    const __nv_bfloat16* Wl = (MODE == 0) ? g_WtH1l : (MODE == 2) ? g_WtN1l : g_WtN2l;

    float d[8][4];
#pragma unroll
    for (int nf = 0; nf < 8; nf++)
#pragma unroll
        for (int e = 0; e < 4; e++) d[nf][e] = 0.f;

    const uint32_t uAh = s2u(Ah), uAl = s2u(Al), uBh = s2u(Bh), uBl = s2u(Bl);

    for (int ks = 0; ks < KTOT; ks += 32) {
        const float* Asrc;
        int koff, lda;
        if (MODE == 2) {
            lda = 128;
            if (ks < 128) { Asrc = A0;  koff = ks; }
            else          { Asrc = g_S; koff = ks - 128; }
        } else if (MODE == 3) {
            Asrc = g_T2; lda = 128; koff = ks;
        } else {
            Asrc = A0; lda = 64; koff = ks;
        }
#pragma unroll
        for (int it = 0; it < 2; it++) {
            int q = tid + it * 256;
            int m = q >> 3, k4 = q & 7;
            float4 v = make_float4(0.f, 0.f, 0.f, 0.f);
            if (m0 + m < Mrows)
                v = ((const float4*)(Asrc + (long long)(m0 + m) * lda + koff))[k4];
            split_store(Ah, Al, m * AN_STR + k4 * 4, v);
        }
#pragma unroll
        for (int it = 0; it < 4; it++) {
            int q = tid + it * 256;
            int row = q >> 5, c = q & 31;
            int off = row * BN_STR + c * 4;
            *(uint2*)(Bh + off) = *(const uint2*)(Wh + (ks + row) * 128 + c * 4);
            *(uint2*)(Bl + off) = *(const uint2*)(Wl + (ks + row) * 128 + c * 4);
        }
        __syncthreads();

#pragma unroll
        for (int kc = 0; kc < 2; kc++) {
            uint32_t ah[4], al[4];
            uint32_t aoff = (uint32_t)(((wm + (lane & 15)) * AN_STR +
                                        kc * 16 + ((lane >> 4) << 3)) * 2);
            ldm4(ah, uAh + aoff);
            ldm4(al, uAl + aoff);
#pragma unroll
            for (int nf2 = 0; nf2 < 4; nf2++) {
                uint32_t boff = (uint32_t)(((kc * 16 + (lane & 15)) * BN_STR +
                                            wn + nf2 * 16 + ((lane >> 4) << 3)) * 2);
                uint32_t bh[4], bl[4];
                ldm4t(bh, uBh + boff);
                ldm4t(bl, uBl + boff);
#pragma unroll
                for (int tt = 0; tt < 2; tt++) {
                    float* dd = d[nf2 * 2 + tt];
                    mma16816(dd, ah, bh[2 * tt], bh[2 * tt + 1]);
                    mma16816(dd, ah, bl[2 * tt], bl[2 * tt + 1]);
                    mma16816(dd, al, bh[2 * tt], bh[2 * tt + 1]);
                }
            }
        }
        __syncthreads();
    }

    {
        int rowc = (wid & 3) * 16 + (lane >> 2);
        int colc = wn + 2 * (lane & 3);
#pragma unroll
        for (int nf = 0; nf < 8; nf++) {
            *(float2*)&Cs[rowc * 128 + colc + nf * 8] = make_float2(d[nf][0], d[nf][1]);
            *(float2*)&Cs[(rowc + 8) * 128 + colc + nf * 8] = make_float2(d[nf][2], d[nf][3]);
        }
    }
    __syncthreads();

    const int tx = tid & 15, ty = tid >> 4;
    const int c0 = tx * 8;
    float bloc[8];
#pragma unroll
    for (int j = 0; j < 8; j++) bloc[j] = bias[c0 + j];
    const int is64 = g_is64_b;
#pragma unroll
    for (int rr = 0; rr < 4; rr++) {
        int cs_r = ty * 4 + rr;
        int m = m0 + cs_r;
        if (m < Mrows) {
            const float* cr = Cs + cs_r * 128 + c0;
            float v[8];
            if (MODE == 2) {
                long long g = is64 ? ((const long long*)idx)[m]
                                   : (long long)((const int*)idx)[m];
                float dg = (float)g_deg[m];
                const float* uw = g_UW + g * 128 + c0;
#pragma unroll
                for (int j = 0; j < 8; j++) {
                    float z = cr[j] + bloc[j] + dg * g_cvec[c0 + j] + uw[j];
                    v[j] = (z >= 0.f) ? z : 0.1f * z;
                }
            } else {
#pragma unroll
                for (int j = 0; j < 8; j++) v[j] = cr[j] + bloc[j];
            }
            float* C = (MODE == 0) ? g_H1 : (MODE == 2) ? g_T2 : Cout;
            float4* dst = (float4*)(C + (long long)m * 128 + c0);
            dst[0] = make_float4(v[0], v[1], v[2], v[3]);
            dst[1] = make_float4(v[4], v[5], v[6], v[7]);
        }
    }
}

// ---------------- launch ----------------
extern "C" void kernel_launch(void* const* d_in, const int* in_sizes, int n_in,
                              void* d_out, int out_size) {
    const float* x_h       = (const float*)d_in[0];
    const float* x_g       = (const float*)d_in[1];
    const float* edge_attr = (const float*)d_in[2];
    const float* u         = (const float*)d_in[3];
    const float* W1a       = (const float*)d_in[4];
    const float* b1a       = (const float*)d_in[5];
    const float* W1b       = (const float*)d_in[6];
    const float* b1b       = (const float*)d_in[7];
    const float* W2a       = (const float*)d_in[8];
    const float* b2a       = (const float*)d_in[9];
    const float* W2b       = (const float*)d_in[10];
    const float* b2b       = (const float*)d_in[11];
    const void*  eidx      = d_in[12];
    const void*  batch     = d_in[13];
    float* out = (float*)d_out;

    cudaFuncSetAttribute(k_edge, cudaFuncAttributeMaxDynamicSharedMemorySize, SE_TOT);

    const int gb_n64 = (NGN + 63) / 64;      // 782
    const int gb_edges = NE / 256;           // 6250

    k_zerodetect<<<512, 256>>>(eidx, batch);                              // 0
    k_prep<<<132, 128>>>(W1a, W1b, W2a, W2b, b1b, u);                    // 1
    k_split<<<(57344 + 255) / 256, 256>>>();                              // 2
    k_tg<64, 0><<<gb_n64, 256>>>(x_h, b1a, nullptr, NHN, nullptr);       // 3
    k_edge<<<gb_edges, 256, SE_TOT>>>(edge_attr, eidx);                   // 4
    k_tg<256, 2><<<gb_n64, 256>>>(x_g, b2a, nullptr, NGN, batch);        // 5
    k_tg<128, 3><<<gb_n64, 256>>>(nullptr, b2b, out, NGN, nullptr);      // 6
}

// round 15
// speedup vs baseline: 1.4226x; 1.4226x over previous
#include <cuda_runtime.h>
#include <cuda_bf16.h>
#include <cstdint>

#define NHN 50000
#define NGN 50000
#define NE  1600000
#define NGR 16

// ---------------- scratch (device globals; no allocations) ----------------
__device__ __align__(16) float g_H1[(size_t)NHN * 128];   // x_h@W1aL^T + b1a
__device__ __align__(16) float g_S [(size_t)NGN * 128];   // sum of leaky(z_e) per target
__device__ __align__(16) float g_T2[(size_t)NGN * 128];   // leaky(node-MLP stage1)
__device__ __align__(16) float g_WtH1[64 * 128];          // W1a[:, :64]^T (fp32 staging)
__device__ __align__(16) float g_WtN1[256 * 128];         // staging
__device__ __align__(16) float g_WtN2[128 * 128];         // staging
__device__ __align__(16) __nv_bfloat16 g_WtEh[64 * 128];  // W1a[:,64:]^T hi
__device__ __align__(16) __nv_bfloat16 g_WtEl[64 * 128];  // lo
__device__ __align__(16) __nv_bfloat16 g_WtH1h[64 * 128];
__device__ __align__(16) __nv_bfloat16 g_WtH1l[64 * 128];
__device__ __align__(16) __nv_bfloat16 g_WtN1h[256 * 128];
__device__ __align__(16) __nv_bfloat16 g_WtN1l[256 * 128];
__device__ __align__(16) __nv_bfloat16 g_WtN2h[128 * 128];
__device__ __align__(16) __nv_bfloat16 g_WtN2l[128 * 128];
__device__ __align__(16) float g_cvec[128];
__device__ __align__(16) float g_UW[NGR * 128];
__device__ int g_deg[NGN];
__device__ int g_is64_e;
__device__ int g_is64_b;

// ---------------- mma helpers ----------------
__device__ __forceinline__ uint32_t s2u(const void* p) {
    return (uint32_t)__cvta_generic_to_shared(p);
}
__device__ __forceinline__ void ldm4(uint32_t* r, uint32_t addr) {
    asm volatile("ldmatrix.sync.aligned.m8n8.x4.shared.b16 {%0,%1,%2,%3}, [%4];"
                 : "=r"(r[0]), "=r"(r[1]), "=r"(r[2]), "=r"(r[3]) : "r"(addr));
}
__device__ __forceinline__ void ldm4t(uint32_t* r, uint32_t addr) {
    asm volatile("ldmatrix.sync.aligned.m8n8.x4.trans.shared.b16 {%0,%1,%2,%3}, [%4];"
                 : "=r"(r[0]), "=r"(r[1]), "=r"(r[2]), "=r"(r[3]) : "r"(addr));
}
__device__ __forceinline__ void mma16816(float* d, const uint32_t* a, uint32_t b0, uint32_t b1) {
    asm volatile("mma.sync.aligned.m16n8k16.row.col.f32.bf16.bf16.f32 "
                 "{%0,%1,%2,%3}, {%4,%5,%6,%7}, {%8,%9}, {%0,%1,%2,%3};"
                 : "+f"(d[0]), "+f"(d[1]), "+f"(d[2]), "+f"(d[3])
                 : "r"(a[0]), "r"(a[1]), "r"(a[2]), "r"(a[3]), "r"(b0), "r"(b1));
}
__device__ __forceinline__ uint32_t cvt2bf(float lo, float hi) {
    uint32_t r;
    asm("cvt.rn.bf16x2.f32 %0, %1, %2;" : "=r"(r) : "f"(hi), "f"(lo));
    return r;
}

// ---------------- zero scratch + dtype detection ----------------
__global__ void k_zerodetect(const void* eidx, const void* batch) {
    if (blockIdx.x == 0 && threadIdx.x == 0) {
        const unsigned* p = (const unsigned*)eidx;
        int is64 = 1;
        for (int i = 0; i < 32; i++) {
            unsigned lo = p[2 * i], hi = p[2 * i + 1];
            if (hi != 0u || lo >= (unsigned)NHN) { is64 = 0; break; }
        }
        g_is64_e = is64;
        const unsigned* q = (const unsigned*)batch;
        int b64 = 1;
        for (int i = 0; i < 32; i++) {
            unsigned lo = q[2 * i], hi = q[2 * i + 1];
            if (hi != 0u || lo >= (unsigned)NGR) { b64 = 0; break; }
        }
        g_is64_b = b64;
    }
    long long n4 = (long long)NGN * 128 / 4;
    long long stride = (long long)gridDim.x * blockDim.x;
    for (long long i = (long long)blockIdx.x * blockDim.x + threadIdx.x; i < n4; i += stride)
        ((float4*)g_S)[i] = make_float4(0.f, 0.f, 0.f, 0.f);
    for (long long i = (long long)blockIdx.x * blockDim.x + threadIdx.x; i < NGN; i += stride)
        g_deg[i] = 0;
}

// ---------------- weight precompute / transposes ----------------
__global__ void k_prep(const float* __restrict__ W1a, const float* __restrict__ W1b,
                       const float* __restrict__ W2a, const float* __restrict__ W2b,
                       const float* __restrict__ b1b, const float* __restrict__ u) {
    int b = blockIdx.x, t = threadIdx.x;
    if (b < 128) {
        __shared__ float wrow[128];
        wrow[t] = W2a[b * 320 + 128 + t];
        __syncthreads();
        float s = 0.f;
        for (int p = 0; p < 128; p++) s += wrow[p] * W1b[p * 128 + t];
        g_WtN1[(128 + t) * 128 + b] = s;
        if (t == 0) {
            float c = 0.f;
            for (int p = 0; p < 128; p++) c += wrow[p] * b1b[p];
            g_cvec[b] = c;
        }
    } else if (b == 128) {
        for (int i = t; i < 64 * 128; i += 128) {
            int k = i >> 7, j = i & 127;
            g_WtH1[i] = W1a[j * 128 + k];
            float w = W1a[j * 128 + 64 + k];
            __nv_bfloat16 h = __float2bfloat16(w);
            g_WtEh[i] = h;
            g_WtEl[i] = __float2bfloat16(w - __bfloat162float(h));
        }
    } else if (b == 129) {
        for (int i = t; i < 128 * 128; i += 128) {
            int k = i >> 7, j = i & 127;
            g_WtN1[i] = W2a[j * 320 + k];
        }
    } else if (b == 130) {
        for (int i = t; i < 128 * 128; i += 128) {
            int k = i >> 7, j = i & 127;
            g_WtN2[i] = W2b[j * 128 + k];
        }
    } else {
        for (int i = t; i < NGR * 128; i += 128) {
            int g = i >> 7, j = i & 127;
            float s = 0.f;
            for (int k = 0; k < 64; k++) s += u[g * 64 + k] * W2a[j * 320 + 256 + k];
            g_UW[i] = s;
        }
    }
}

// split staged fp32 weights into bf16 hi/lo (after k_prep)
__global__ void k_split() {
    int i = blockIdx.x * blockDim.x + threadIdx.x;
    if (i < 8192) {
        float w = g_WtH1[i];
        __nv_bfloat16 h = __float2bfloat16(w);
        g_WtH1h[i] = h;
        g_WtH1l[i] = __float2bfloat16(w - __bfloat162float(h));
    } else if (i < 8192 + 32768) {
        int j = i - 8192;
        float w = g_WtN1[j];
        __nv_bfloat16 h = __float2bfloat16(w);
        g_WtN1h[j] = h;
        g_WtN1l[j] = __float2bfloat16(w - __bfloat162float(h));
    } else if (i < 8192 + 32768 + 16384) {
        int j = i - 8192 - 32768;
        float w = g_WtN2[j];
        __nv_bfloat16 h = __float2bfloat16(w);
        g_WtN2h[j] = h;
        g_WtN2l[j] = __float2bfloat16(w - __bfloat162float(h));
    }
}

// ---------------- shared split-store helper ----------------
__device__ __forceinline__ void split_store(__nv_bfloat16* Ah, __nv_bfloat16* Al,
                                            int off, float4 v) {
    uint32_t ph01 = cvt2bf(v.x, v.y);
    uint32_t ph23 = cvt2bf(v.z, v.w);
    float l0 = v.x - __uint_as_float(ph01 << 16);
    float l1 = v.y - __uint_as_float(ph01 & 0xffff0000u);
    float l2 = v.z - __uint_as_float(ph23 << 16);
    float l3 = v.w - __uint_as_float(ph23 & 0xffff0000u);
    uint32_t pl01 = cvt2bf(l0, l1);
    uint32_t pl23 = cvt2bf(l2, l3);
    *(uint2*)(Ah + off) = make_uint2(ph01, ph23);
    *(uint2*)(Al + off) = make_uint2(pl01, pl23);
}

// ================= tensor-core edge kernel (R13 structure, padded Cs) =================
#define A_STR 40
#define B_STR 136
#define CS_STR 132          // 128 + 4 pad: row stride ≢ 0 mod 32 banks -> conflict-free Cs
#define SM_AL 10240
#define SM_BH 20480
#define SM_BL 29184
#define SM_TOT 37888        // Cs = 64*132*4 = 33792 fits in the union

__launch_bounds__(256, 2)
__global__ void k_edge(const float* __restrict__ EA, const void* __restrict__ eidx) {
    __shared__ __align__(16) char sm[SM_TOT];
    __nv_bfloat16* Ah = (__nv_bfloat16*)sm;
    __nv_bfloat16* Al = (__nv_bfloat16*)(sm + SM_AL);
    __nv_bfloat16* Bh = (__nv_bfloat16*)(sm + SM_BH);
    __nv_bfloat16* Bl = (__nv_bfloat16*)(sm + SM_BL);
    float* Cs = (float*)sm;

    const int tid = threadIdx.x;
    const int lane = tid & 31, wid = tid >> 5;
    const int wm = (wid & 3) * 32;
    const int wn = (wid >> 2) * 64;
    const long long m0 = (long long)blockIdx.x * 128;

    float d[2][8][4];
#pragma unroll
    for (int mf = 0; mf < 2; mf++)
#pragma unroll
        for (int nf = 0; nf < 8; nf++)
#pragma unroll
            for (int e = 0; e < 4; e++) d[mf][nf][e] = 0.f;

    const uint32_t uAh = s2u(Ah), uAl = s2u(Al), uBh = s2u(Bh), uBl = s2u(Bl);

    for (int ks = 0; ks < 64; ks += 32) {
#pragma unroll
        for (int it = 0; it < 4; it++) {
            int q = tid + it * 256;
            int m = q >> 3, k4 = q & 7;
            float4 v = ((const float4*)(EA + (m0 + m) * 64 + ks))[k4];
            split_store(Ah, Al, m * A_STR + k4 * 4, v);
        }
#pragma unroll
        for (int it = 0; it < 4; it++) {
            int q = tid + it * 256;
            int row = q >> 5, c = q & 31;
            int off = row * B_STR + c * 4;
            *(uint2*)(Bh + off) = *(const uint2*)(g_WtEh + (ks + row) * 128 + c * 4);
            *(uint2*)(Bl + off) = *(const uint2*)(g_WtEl + (ks + row) * 128 + c * 4);
        }
        __syncthreads();

#pragma unroll
        for (int kc = 0; kc < 2; kc++) {
            uint32_t ah[2][4], al[2][4];
#pragma unroll
            for (int mf = 0; mf < 2; mf++) {
                uint32_t aoff = (uint32_t)(((wm + mf * 16 + (lane & 15)) * A_STR +
                                            kc * 16 + ((lane >> 4) << 3)) * 2);
                ldm4(ah[mf], uAh + aoff);
                ldm4(al[mf], uAl + aoff);
            }
#pragma unroll
            for (int nf2 = 0; nf2 < 4; nf2++) {
                uint32_t boff = (uint32_t)(((kc * 16 + (lane & 15)) * B_STR +
                                            wn + nf2 * 16 + ((lane >> 4) << 3)) * 2);
                uint32_t bh[4], bl[4];
                ldm4t(bh, uBh + boff);
                ldm4t(bl, uBl + boff);
#pragma unroll
                for (int mf = 0; mf < 2; mf++) {
#pragma unroll
                    for (int tt = 0; tt < 2; tt++) {
                        float* dd = d[mf][nf2 * 2 + tt];
                        mma16816(dd, ah[mf], bh[2 * tt], bh[2 * tt + 1]);
                        mma16816(dd, ah[mf], bl[2 * tt], bl[2 * tt + 1]);
                        mma16816(dd, al[mf], bh[2 * tt], bh[2 * tt + 1]);
                    }
                }
            }
        }
        __syncthreads();
    }

    const int is64 = g_is64_e;
    const int tx = tid & 15, ty = tid >> 4;
    const int c0 = tx * 8;
#pragma unroll
    for (int p = 0; p < 2; p++) {
        int rowc = (wid & 3) * 16 + (lane >> 2);
        int colc = wn + 2 * (lane & 3);
#pragma unroll
        for (int nf = 0; nf < 8; nf++) {
            *(float2*)&Cs[rowc * CS_STR + colc + nf * 8] = make_float2(d[p][nf][0], d[p][nf][1]);
            *(float2*)&Cs[(rowc + 8) * CS_STR + colc + nf * 8] = make_float2(d[p][nf][2], d[p][nf][3]);
        }
        __syncthreads();
#pragma unroll
        for (int rr = 0; rr < 4; rr++) {
            int cs_r = ty * 4 + rr;
            long long er = m0 + ((cs_r >> 4) << 5) + p * 16 + (cs_r & 15);
            long long s, t;
            if (is64) {
                s = ((const long long*)eidx)[er];
                t = ((const long long*)eidx)[(long long)NE + er];
            } else {
                s = ((const int*)eidx)[er];
                t = ((const int*)eidx)[(long long)NE + er];
            }
            const float4* h = (const float4*)(g_H1 + s * 128 + c0);
            float4 h0 = h[0], h1 = h[1];
            const float* cr = Cs + cs_r * CS_STR + c0;
            float v[8];
            v[0] = cr[0] + h0.x; v[1] = cr[1] + h0.y; v[2] = cr[2] + h0.z; v[3] = cr[3] + h0.w;
            v[4] = cr[4] + h1.x; v[5] = cr[5] + h1.y; v[6] = cr[6] + h1.z; v[7] = cr[7] + h1.w;
#pragma unroll
            for (int j = 0; j < 8; j++) v[j] = (v[j] >= 0.f) ? v[j] : 0.1f * v[j];
            float* dst = g_S + t * 128 + c0;
            asm volatile("red.global.add.v4.f32 [%0], {%1,%2,%3,%4};"
                         :: "l"(dst), "f"(v[0]), "f"(v[1]), "f"(v[2]), "f"(v[3]) : "memory");
            asm volatile("red.global.add.v4.f32 [%0], {%1,%2,%3,%4};"
                         :: "l"(dst + 4), "f"(v[4]), "f"(v[5]), "f"(v[6]), "f"(v[7]) : "memory");
            if (tx == 0) atomicAdd(&g_deg[(int)t], 1);
        }
        __syncthreads();
    }
}

// ================= tensor-core node GEMM: 64x128 block tile (padded Cs) =================
#define AN_STR 40
#define BN_STR 136
#define NSM_AL 5120
#define NSM_BH 10240
#define NSM_BL 18944
#define NCS_STR 132
#define NSM_TOT 33792   // Cs 64*132*4 overlays everything

template <int KTOT, int MODE>
__launch_bounds__(256, 2)
__global__ void k_tg(const float* __restrict__ A0, const float* __restrict__ bias,
                     float* __restrict__ Cout, int Mrows, const void* __restrict__ idx) {
    __shared__ __align__(16) char sm[NSM_TOT];
    __nv_bfloat16* Ah = (__nv_bfloat16*)sm;
    __nv_bfloat16* Al = (__nv_bfloat16*)(sm + NSM_AL);
    __nv_bfloat16* Bh = (__nv_bfloat16*)(sm + NSM_BH);
    __nv_bfloat16* Bl = (__nv_bfloat16*)(sm + NSM_BL);
    float* Cs = (float*)sm;

    const int tid = threadIdx.x;
    const int lane = tid & 31, wid = tid >> 5;
    const int wm = (wid & 3) * 16;
    const int wn = (wid >> 2) * 64;
    const int m0 = blockIdx.x * 64;

    const __nv_bfloat16* Wh = (MODE == 0) ? g_WtH1h : (MODE == 2) ? g_WtN1h : g_WtN2h;
    const __nv_bfloat16* Wl = (MODE == 0) ? g_WtH1l : (MODE == 2) ? g_WtN1l : g_WtN2l;

    float d[8][4];
#pragma unroll
    for (int nf = 0; nf < 8; nf++)
#pragma unroll
        for (int e = 0; e < 4; e++) d[nf][e] = 0.f;

    const uint32_t uAh = s2u(Ah), uAl = s2u(Al), uBh = s2u(Bh), uBl = s2u(Bl);

    for (int ks = 0; ks < KTOT; ks += 32) {
        const float* Asrc;
        int koff, lda;
        if (MODE == 2) {
            lda = 128;
            if (ks < 128) { Asrc = A0;  koff = ks; }
            else          { Asrc = g_S; koff = ks - 128; }
        } else if (MODE == 3) {
            Asrc = g_T2; lda = 128; koff = ks;
        } else {
            Asrc = A0; lda = 64; koff = ks;
        }
#pragma unroll
        for (int it = 0; it < 2; it++) {
            int q = tid + it * 256;
            int m = q >> 3, k4 = q & 7;
            float4 v = make_float4(0.f, 0.f, 0.f, 0.f);
            if (m0 + m < Mrows)
                v = ((const float4*)(Asrc + (long long)(m0 + m) * lda + koff))[k4];
            split_store(Ah, Al, m * AN_STR + k4 * 4, v);
        }
#pragma unroll
        for (int it = 0; it < 4; it++) {
            int q = tid + it * 256;
            int row = q >> 5, c = q & 31;
            int off = row * BN_STR + c * 4;
            *(uint2*)(Bh + off) = *(const uint2*)(Wh + (ks + row) * 128 + c * 4);
            *(uint2*)(Bl + off) = *(const uint2*)(Wl + (ks + row) * 128 + c * 4);
        }
        __syncthreads();

#pragma unroll
        for (int kc = 0; kc < 2; kc++) {
            uint32_t ah[4], al[4];
            uint32_t aoff = (uint32_t)(((wm + (lane & 15)) * AN_STR +
                                        kc * 16 + ((lane >> 4) << 3)) * 2);
            ldm4(ah, uAh + aoff);
            ldm4(al, uAl + aoff);
#pragma unroll
            for (int nf2 = 0; nf2 < 4; nf2++) {
                uint32_t boff = (uint32_t)(((kc * 16 + (lane & 15)) * BN_STR +
                                            wn + nf2 * 16 + ((lane >> 4) << 3)) * 2);
                uint32_t bh[4], bl[4];
                ldm4t(bh, uBh + boff);
                ldm4t(bl, uBl + boff);
#pragma unroll
                for (int tt = 0; tt < 2; tt++) {
                    float* dd = d[nf2 * 2 + tt];
                    mma16816(dd, ah, bh[2 * tt], bh[2 * tt + 1]);
                    mma16816(dd, ah, bl[2 * tt], bl[2 * tt + 1]);
                    mma16816(dd, al, bh[2 * tt], bh[2 * tt + 1]);
                }
            }
        }
        __syncthreads();
    }

    {
        int rowc = (wid & 3) * 16 + (lane >> 2);
        int colc = wn + 2 * (lane & 3);
#pragma unroll
        for (int nf = 0; nf < 8; nf++) {
            *(float2*)&Cs[rowc * NCS_STR + colc + nf * 8] = make_float2(d[nf][0], d[nf][1]);
            *(float2*)&Cs[(rowc + 8) * NCS_STR + colc + nf * 8] = make_float2(d[nf][2], d[nf][3]);
        }
    }
    __syncthreads();

    const int tx = tid & 15, ty = tid >> 4;
    const int c0 = tx * 8;
    float bloc[8];
#pragma unroll
    for (int j = 0; j < 8; j++) bloc[j] = bias[c0 + j];
    const int is64 = g_is64_b;
#pragma unroll
    for (int rr = 0; rr < 4; rr++) {
        int cs_r = ty * 4 + rr;
        int m = m0 + cs_r;
        if (m < Mrows) {
            const float* cr = Cs + cs_r * NCS_STR + c0;
            float v[8];
            if (MODE == 2) {
                long long g = is64 ? ((const long long*)idx)[m]
                                   : (long long)((const int*)idx)[m];
                float dg = (float)g_deg[m];
                const float* uw = g_UW + g * 128 + c0;
#pragma unroll
                for (int j = 0; j < 8; j++) {
                    float z = cr[j] + bloc[j] + dg * g_cvec[c0 + j] + uw[j];
                    v[j] = (z >= 0.f) ? z : 0.1f * z;
                }
            } else {
#pragma unroll
                for (int j = 0; j < 8; j++) v[j] = cr[j] + bloc[j];
            }
            float* C = (MODE == 0) ? g_H1 : (MODE == 2) ? g_T2 : Cout;
            float4* dst = (float4*)(C + (long long)m * 128 + c0);
            dst[0] = make_float4(v[0], v[1], v[2], v[3]);
            dst[1] = make_float4(v[4], v[5], v[6], v[7]);
        }
    }
}

// ---------------- launch ----------------
extern "C" void kernel_launch(void* const* d_in, const int* in_sizes, int n_in,
                              void* d_out, int out_size) {
    const float* x_h       = (const float*)d_in[0];
    const float* x_g       = (const float*)d_in[1];
    const float* edge_attr = (const float*)d_in[2];
    const float* u         = (const float*)d_in[3];
    const float* W1a       = (const float*)d_in[4];
    const float* b1a       = (const float*)d_in[5];
    const float* W1b       = (const float*)d_in[6];
    const float* b1b       = (const float*)d_in[7];
    const float* W2a       = (const float*)d_in[8];
    const float* b2a       = (const float*)d_in[9];
    const float* W2b       = (const float*)d_in[10];
    const float* b2b       = (const float*)d_in[11];
    const void*  eidx      = d_in[12];
    const void*  batch     = d_in[13];
    float* out = (float*)d_out;

    const int gb_n64 = (NGN + 63) / 64;      // 782
    const int gb_edges = NE / 128;           // 12500

    k_zerodetect<<<512, 256>>>(eidx, batch);                              // 0
    k_prep<<<132, 128>>>(W1a, W1b, W2a, W2b, b1b, u);                    // 1
    k_split<<<(57344 + 255) / 256, 256>>>();                              // 2
    k_tg<64, 0><<<gb_n64, 256>>>(x_h, b1a, nullptr, NHN, nullptr);       // 3
    k_edge<<<gb_edges, 256>>>(edge_attr, eidx);                           // 4
    k_tg<256, 2><<<gb_n64, 256>>>(x_g, b2a, nullptr, NGN, batch);        // 5
    k_tg<128, 3><<<gb_n64, 256>>>(nullptr, b2b, out, NGN, nullptr);      // 6
}